// round 8
// baseline (speedup 1.0000x reference)
#include <cuda_runtime.h>
#include <cuda.h>
#include <cuda_fp16.h>
#include <math.h>
#include <stdint.h>
#include <dlfcn.h>

// ---------------- problem constants -----------------------------------------
#define LSEQ  4096
#define NFFT  8192
#define NBINS 512
#define BH    6144         // B*H
#define HDIM  768
#define M1    6912         // BH + HDIM (k rows ride along in GEMM1)
#define K1    4096
#define N1    1024         // 512 bins x (re, im)
#define M2    6144
#define K2    1024
#define N2    4096

// sm_103a feature pass? (tcgen05/TMEM only exist in arch-specific compile)
#if defined(__CUDA_ARCH__) && (__CUDA_ARCH__ >= 1000) && \
    (defined(__CUDA_ARCH_FEAT_SM103_ALL) || defined(__CUDA_ARCH_SPECIFIC__) || \
     defined(__CUDA_ARCH_FAMILY_SPECIFIC__))
#define HAS_TCGEN05 1
#else
#define HAS_TCGEN05 0
#endif

// ---------------- device scratch (no allocs allowed) ------------------------
__device__ __align__(16) __half g_A [(size_t)M1 * K1];   // fallback only
__device__ __align__(16) __half g_Wf[(size_t)N1 * K1];   // [N1,K1] fwd DFT weights (K-major)
__device__ __align__(16) __half g_X [(size_t)M1 * N1];   // spectra, fp16
__device__ __align__(16) __half g_Z [(size_t)M2 * K2];   // scaled product spectrum
__device__ __align__(16) __half g_Wi[(size_t)N2 * K2];   // [N2,K2] inv DFT weights (K-major)

// ---------------- generic PTX helpers ----------------------------------------
__device__ __forceinline__ uint32_t smem_u32(const void* p) {
    return (uint32_t)__cvta_generic_to_shared(p);
}
__device__ __forceinline__ void cp16(uint32_t dst, const void* src) {
    asm volatile("cp.async.cg.shared.global [%0], [%1], 16;\n" :: "r"(dst), "l"(src));
}
__device__ __forceinline__ void cp_commit() {
    asm volatile("cp.async.commit_group;\n" ::: "memory");
}
template <int N>
__device__ __forceinline__ void cp_wait() {
    asm volatile("cp.async.wait_group %0;\n" :: "n"(N) : "memory");
}
__device__ __forceinline__ uint32_t cluster_rank() {
    uint32_t r; asm("mov.u32 %0, %%cluster_ctarank;" : "=r"(r)); return r;
}
#define SWZ(off) ((off) ^ (((off) >> 3) & 0x70))

#define MBARRIER_INIT(mbar, count) \
    asm volatile("mbarrier.init.shared.b64 [%0], %1;" :: "r"((uint32_t)(mbar)), "r"((uint32_t)(count)) : "memory")
#define MBARRIER_ARRIVE_LEADER(mbar) \
    asm volatile("{\n\t.reg .b32 la;\n\t" \
        "and.b32 la, %0, 0xFEFFFFFF;\n\t" \
        "mbarrier.arrive.shared::cluster.b64 _, [la];\n\t}" \
        :: "r"((uint32_t)(mbar)) : "memory")
#define MBARRIER_EXPECT_TX(mbar, bytes) \
    asm volatile("mbarrier.arrive.expect_tx.shared.b64 _, [%0], %1;" \
                 :: "r"((uint32_t)(mbar)), "r"((uint32_t)(bytes)) : "memory")
#define MBARRIER_WAIT_PARITY(mbar, parity) do {                                   \
    uint32_t _m = (uint32_t)(mbar); uint32_t _p = (uint32_t)(parity); uint32_t _d; \
    asm volatile("{\n\t.reg .pred p;\n\t"                                         \
        "mbarrier.try_wait.parity.acquire.cta.shared::cta.b64 p, [%1], %2;\n\t"   \
        "selp.b32 %0, 1, 0, p;\n\t}"                                              \
        : "=r"(_d) : "r"(_m), "r"(_p) : "memory");                                \
    if (!_d) {                                                                    \
        asm volatile("{\n\t.reg .pred P1;\n\t"                                    \
            "WL_%=:\n\t"                                                          \
            "mbarrier.try_wait.parity.acquire.cta.shared::cta.b64 P1, [%0], %1, 0x989680;\n\t" \
            "@P1 bra.uni WD_%=;\n\t"                                              \
            "bra.uni WL_%=;\n\t"                                                  \
            "WD_%=:\n\t}" :: "r"(_m), "r"(_p) : "memory");                        \
    } } while (0)
#define CLUSTER_SYNC() do { \
    asm volatile("barrier.cluster.arrive.aligned;" ::: "memory"); \
    asm volatile("barrier.cluster.wait.aligned;" ::: "memory"); } while (0)

// ---------------- setup kernels ----------------------------------------------
#define TWO_PI_OVER_N 7.6699039e-4f   // 2*pi/8192

// fallback only: A = [x;k] fp16
__global__ void convert_inputs(const float2* __restrict__ x2, const float2* __restrict__ k2) {
    size_t i = (size_t)blockIdx.x * 256 + threadIdx.x;
    const size_t XN2 = (size_t)BH * LSEQ / 2;
    float2 v = (i < XN2) ? x2[i] : k2[i - XN2];
    ((__half2*)g_A)[i] = __floats2half2_rn(v.x, v.y);
}

// Wf[n][k] (K-major [N1,K1]): n=2f -> cos(2pi f k/8192); n=2f+1 -> -sin
__global__ void fill_Wf() {
    int idx = blockIdx.x * 256 + threadIdx.x;   // N1*K1/8 threads
    int n = idx >> 9, c = (idx & 511) << 3;
    int f = n >> 1, odd = n & 1;
    __half h[8];
#pragma unroll
    for (int j = 0; j < 8; j++) {
        int m = (f * (c + j)) & (NFFT - 1);
        float sv, cv;
        __sincosf((float)m * TWO_PI_OVER_N, &sv, &cv);
        h[j] = __float2half_rn(odd ? -sv : cv);
    }
    *(uint4*)(g_Wf + (size_t)n * K1 + c) = *(uint4*)h;
}

// Fused middle kernel: pointwise Z + fill Wi (independent work, one launch)
#define PW_BLOCKS 3072
__global__ void mid_pointwise_fillwi() {
    if (blockIdx.x < PW_BLOCKS) {
        int idx = blockIdx.x * 256 + threadIdx.x;   // BH*NBINS/4 threads
        int r = idx >> 7, f4 = (idx & 127) << 2;
        int h = r % HDIM;
        uint4 xu = *(const uint4*)(g_X + (size_t)r * N1 + 2 * f4);
        uint4 ku = *(const uint4*)(g_X + (size_t)(BH + h) * N1 + 2 * f4);
        const __half2* xh = (const __half2*)&xu;
        const __half2* kh = (const __half2*)&ku;
        uint4 zu;
        __half2* zh = (__half2*)&zu;
#pragma unroll
        for (int j = 0; j < 4; j++) {
            float2 X = __half22float2(xh[j]);
            float2 K = __half22float2(kh[j]);
            float alpha = ((f4 + j) == 0) ? (1.0f / 8192.0f) : (2.0f / 8192.0f);
            float Zr = alpha * (X.x * K.x - X.y * K.y);
            float Zi = alpha * (X.x * K.y + X.y * K.x);
            zh[j] = __floats2half2_rn(Zr, -Zi);
        }
        *(uint4*)(g_Z + (size_t)r * K2 + 2 * f4) = zu;
    } else {
        int idx = (blockIdx.x - PW_BLOCKS) * 256 + threadIdx.x;  // N2*K2/8 threads
        int n = idx >> 7, c = (idx & 127) << 3;
        __half h[8];
#pragma unroll
        for (int j = 0; j < 4; j++) {
            int f = (c >> 1) + j;
            int m = (f * n) & (NFFT - 1);
            float sv, cv;
            __sincosf((float)m * TWO_PI_OVER_N, &sv, &cv);
            h[2 * j]     = __float2half_rn(cv);
            h[2 * j + 1] = __float2half_rn(sv);
        }
        *(uint4*)(g_Wi + (size_t)n * K2 + c) = *(uint4*)h;
    }
}

// ================= tcgen05 cg2 + TMA path (sm_103a only) =====================
// C[M,N] = A[M,K] @ B[N,K]^T.  Cluster(2,1,1): M-tile 256 (128 rows/CTA),
// N-tile = BNT*256 via BNT cg2 N=256 MMAs.  BK=64, 4-stage TMA pipeline;
// every tile block is one 16KB SW128 TMA box [64 halves x 128 rows].
constexpr int STG = 4, BK = 64;
constexpr int BLK16K = 16384;
template <int BNT> struct StageCfg {
    static constexpr int STAGE_B = BLK16K + BNT * BLK16K;          // A + B groups
    static constexpr int SMEM_DYN = 2048 + STG * STAGE_B;
};

#if HAS_TCGEN05
static constexpr uint64_t SMEM_DESC_BASE_SW128 =
    (uint64_t(2) << 61) | (uint64_t(1) << 46) | (uint64_t(64) << 32) | (uint64_t(1) << 16);
#define MAKE_SMEM_DESC(addr) (SMEM_DESC_BASE_SW128 | ((uint64_t)((addr) >> 4) & 0x3FFF))

#define TCGEN05_ALLOC_CG2(smem_addr, ncols) \
    asm volatile("tcgen05.alloc.cta_group::2.sync.aligned.shared::cta.b32 [%0], %1;" \
                 :: "r"((uint32_t)(smem_addr)), "r"((uint32_t)(ncols)) : "memory")
#define TCGEN05_DEALLOC_CG2(tmem, ncols) \
    asm volatile("tcgen05.dealloc.cta_group::2.sync.aligned.b32 %0, %1;" :: "r"(tmem), "r"((uint32_t)(ncols)))
#define TCGEN05_RELINQ_CG2() \
    asm volatile("tcgen05.relinquish_alloc_permit.cta_group::2.sync.aligned;")
#define TCGEN05_COMMIT_MC_CG2(mbar, mask) \
    asm volatile("tcgen05.commit.cta_group::2.mbarrier::arrive::one.shared::cluster.multicast::cluster.b64 [%0], %1;" \
                 :: "r"((uint32_t)(mbar)), "h"((uint16_t)(mask)) : "memory")
#define TCGEN05_FENCE_AFTER() asm volatile("tcgen05.fence::after_thread_sync;" ::: "memory")
#define TCGEN05_WAIT_LD()     asm volatile("tcgen05.wait::ld.sync.aligned;" ::: "memory")
#define TCGEN05_LD_X32(r, addr) \
    asm volatile("tcgen05.ld.sync.aligned.32x32b.x32.b32 "                         \
        "{%0, %1, %2, %3, %4, %5, %6, %7, %8, %9, %10, %11, %12, %13, %14, %15, "  \
        " %16, %17, %18, %19, %20, %21, %22, %23, %24, %25, %26, %27, %28, %29, %30, %31}, [%32];" \
        : "=r"((r)[0]),  "=r"((r)[1]),  "=r"((r)[2]),  "=r"((r)[3]),               \
          "=r"((r)[4]),  "=r"((r)[5]),  "=r"((r)[6]),  "=r"((r)[7]),               \
          "=r"((r)[8]),  "=r"((r)[9]),  "=r"((r)[10]), "=r"((r)[11]),              \
          "=r"((r)[12]), "=r"((r)[13]), "=r"((r)[14]), "=r"((r)[15]),              \
          "=r"((r)[16]), "=r"((r)[17]), "=r"((r)[18]), "=r"((r)[19]),              \
          "=r"((r)[20]), "=r"((r)[21]), "=r"((r)[22]), "=r"((r)[23]),              \
          "=r"((r)[24]), "=r"((r)[25]), "=r"((r)[26]), "=r"((r)[27]),              \
          "=r"((r)[28]), "=r"((r)[29]), "=r"((r)[30]), "=r"((r)[31])               \
        : "r"(addr))

// cg2 TMA: both CTAs execute; complete_tx targets the LEADER's barrier (bit 24 cleared)
#define TMA_LOAD_CG2(dst, map, cx, cy, mbar) \
    asm volatile("{\n\t.reg .b32 lb;\n\t" \
        "and.b32 lb, %4, 0xFEFFFFFF;\n\t" \
        "cp.async.bulk.tensor.3d.cta_group::2.shared::cluster.global" \
        ".tile.mbarrier::complete_tx::bytes [%0], [%1, {%2, %3, %5}], [lb];\n\t}" \
        :: "r"((uint32_t)(dst)), "l"(map), "r"((int32_t)(cx)), "r"((int32_t)(cy)), \
           "r"((uint32_t)(mbar)), "r"(0) : "memory")

__device__ __forceinline__ void mma_f16_ss_cg2(uint32_t d, uint64_t ad, uint64_t bd,
                                               uint32_t idesc, uint32_t enable) {
    asm volatile(
        "{\n\t.reg .pred p;\n\t"
        "setp.ne.u32 p, %4, 0;\n\t"
        "tcgen05.mma.cta_group::2.kind::f16 [%0], %1, %2, %3, "
        "{%5, %5, %5, %5, %5, %5, %5, %5}, p;\n\t}"
        :: "r"(d), "l"(ad), "l"(bd), "r"(idesc), "r"(enable), "r"(0u)
        : "memory");
}
#endif // HAS_TCGEN05

// WHICH=1: A = x/k fp32 converted inline by warps 0-6; B = Wf via TMA; C = g_X fp16
// WHICH=2: A = g_Z via TMA; B = Wi via TMA; C = outp fp32
template <int KK, int WHICH, int BNT>
__global__ void __launch_bounds__(256, 1) __cluster_dims__(2, 1, 1)
gemm_tma(const float* __restrict__ xin, const float* __restrict__ kin, float* __restrict__ outp,
         const __grid_constant__ CUtensorMap tmA, const __grid_constant__ CUtensorMap tmB) {
#if HAS_TCGEN05
    extern __shared__ char smem[];
    constexpr int NN = (WHICH == 1) ? N1 : N2;
    constexpr int KT = KK / BK;
    constexpr int BNTOT = BNT * 256;                 // cluster N-tile
    constexpr int STAGE_B = StageCfg<BNT>::STAGE_B;
    constexpr uint32_t TX = (uint32_t)(2 * BNT * BLK16K) + ((WHICH == 2) ? 2 * BLK16K : 0);

    const uint32_t sb = (smem_u32(smem) + 1023u) & ~1023u;
    const uint32_t mb_full  = sb + 8;    // STG x 8B
    const uint32_t mb_empty = sb + 40;
    const uint32_t mb_done  = sb + 72;
    const uint32_t tb = sb + 1024;

    const int tid = threadIdx.x, wid = tid >> 5, lane = tid & 31;
    const uint32_t rank = cluster_rank();
    const int bn = blockIdx.x >> 1;
    const int mbase = blockIdx.y * 256 + (int)rank * 128;

    if (tid == 0) {
        for (int s = 0; s < STG; s++) {
            MBARRIER_INIT(mb_full + 8 * s, (WHICH == 1) ? 15 : 1);
            MBARRIER_INIT(mb_empty + 8 * s, 1);
        }
        MBARRIER_INIT(mb_done, 1);
    }
    if (wid == 4) { TCGEN05_ALLOC_CG2(sb, 512); TCGEN05_RELINQ_CG2(); }
    __syncthreads();
    uint32_t tmem;
    asm volatile("ld.shared.b32 %0, [%1];" : "=r"(tmem) : "r"(sb));
    CLUSTER_SYNC();

    const bool producer = (WHICH == 1) ? (wid < 7) : (tid == 0);
    if (producer) {
        const float* asrc32 = nullptr;
        if (WHICH == 1)
            asrc32 = (mbase < BH) ? xin + (size_t)mbase * K1
                                  : kin + (size_t)(mbase - BH) * K1;
        for (int kt = 0; kt < KT; kt++) {
            const int s = kt & (STG - 1);
            MBARRIER_WAIT_PARITY(mb_empty + 8 * s, ((kt / STG) + 1) & 1);
            const int k0 = kt * BK;
            const uint32_t sA = tb + s * STAGE_B;
            const uint32_t sB = sA + BLK16K;

            if (tid == 0) {
                if (rank == 0) MBARRIER_EXPECT_TX(mb_full + 8 * s, TX);
#pragma unroll
                for (int g = 0; g < BNT; g++)
                    TMA_LOAD_CG2(sB + g * BLK16K, &tmB,
                                 k0, bn * BNTOT + g * 256 + (int)rank * 128,
                                 mb_full + 8 * s);
                if (WHICH == 2)
                    TMA_LOAD_CG2(sA, &tmA, k0, mbase, mb_full + 8 * s);
            }
            if (WHICH == 1) {
                // A: 1024 16B-chunks fp32->fp16 over 224 threads
#pragma unroll
                for (int i = 0; i < 5; i++) {
                    int ci = tid + i * 224;
                    if (ci >= 1024) break;
                    int r = ci >> 3, cc = ci & 7;
                    const float4* p = (const float4*)(asrc32 + (size_t)r * K1 + k0 + cc * 8);
                    float4 v0 = p[0], v1 = p[1];
                    __half2 a0 = __floats2half2_rn(v0.x, v0.y);
                    __half2 a1 = __floats2half2_rn(v0.z, v0.w);
                    __half2 a2 = __floats2half2_rn(v1.x, v1.y);
                    __half2 a3 = __floats2half2_rn(v1.z, v1.w);
                    asm volatile("st.shared.v4.b32 [%0], {%1,%2,%3,%4};"
                        :: "r"(sA + SWZ(r * 128 + cc * 16)),
                           "r"(*(uint32_t*)&a0), "r"(*(uint32_t*)&a1),
                           "r"(*(uint32_t*)&a2), "r"(*(uint32_t*)&a3) : "memory");
                }
                asm volatile("fence.proxy.async.shared::cta;" ::: "memory");
                if (lane == 0) MBARRIER_ARRIVE_LEADER(mb_full + 8 * s);
            }
        }
    } else if (rank == 0 && tid == 224) {
        // ------------------------------ MMA issuer ---------------------------
        const uint32_t idesc = (1u << 4) | (32u << 17) | (16u << 24);  // F32, N=256, M=256
        for (int kt = 0; kt < KT; kt++) {
            const int s = kt & (STG - 1);
            MBARRIER_WAIT_PARITY(mb_full + 8 * s, (kt / STG) & 1);
            const uint64_t ad = MAKE_SMEM_DESC(tb + s * STAGE_B);
            const uint64_t bd = MAKE_SMEM_DESC(tb + s * STAGE_B + BLK16K);
#pragma unroll
            for (int j = 0; j < 4; j++) {          // 4 x K=16 per stage
                uint32_t en = (uint32_t)((kt | j) != 0);
#pragma unroll
                for (int g = 0; g < BNT; g++)
                    mma_f16_ss_cg2(tmem + g * 256, ad + 2 * j,
                                   bd + g * 1024 + 2 * j, idesc, en);
            }
            TCGEN05_COMMIT_MC_CG2(mb_empty + 8 * s, 3);
        }
        TCGEN05_COMMIT_MC_CG2(mb_done, 3);
    }

    // ------------------------------ epilogue: all 8 warps ---------------------
    __syncwarp();
    MBARRIER_WAIT_PARITY(mb_done, 0);
    TCGEN05_FENCE_AFTER();
    {
        const int rowl = (wid & 3) * 32 + lane;
        const int half = BNTOT / 2;
        const int cb = (wid >> 2) * half;
        const int grow = mbase + rowl;
#pragma unroll
        for (int c0 = 0; c0 < half; c0 += 32) {
            uint32_t r[32];
            TCGEN05_LD_X32(r, tmem + cb + c0);
            TCGEN05_WAIT_LD();
            if (WHICH == 1) {
                uint4 u[2];
                __half2* hp = (__half2*)u;
#pragma unroll
                for (int q = 0; q < 8; q++)
                    hp[q] = __floats2half2_rn(__uint_as_float(r[2 * q]), __uint_as_float(r[2 * q + 1]));
                __half* dst = g_X + (size_t)grow * NN + bn * BNTOT + cb + c0;
                *(uint4*)(dst)     = u[0];
                *(uint4*)(dst + 8) = u[1];
                uint4 v[2];
                __half2* vp = (__half2*)v;
#pragma unroll
                for (int q = 0; q < 8; q++)
                    vp[q] = __floats2half2_rn(__uint_as_float(r[16 + 2 * q]), __uint_as_float(r[17 + 2 * q]));
                *(uint4*)(dst + 16) = v[0];
                *(uint4*)(dst + 24) = v[1];
            } else {
                float* dst = outp + (size_t)grow * NN + bn * BNTOT + cb + c0;
#pragma unroll
                for (int q = 0; q < 8; q++) {
                    float4 v = make_float4(__uint_as_float(r[4 * q + 0]), __uint_as_float(r[4 * q + 1]),
                                           __uint_as_float(r[4 * q + 2]), __uint_as_float(r[4 * q + 3]));
                    *(float4*)(dst + 4 * q) = v;
                }
            }
        }
    }

    __syncthreads();
    if (wid == 4) TCGEN05_DEALLOC_CG2(tmem, 512);
    CLUSTER_SYNC();
#endif // HAS_TCGEN05
}

// ================= HMMA fallback (compiles everywhere) ========================
__device__ __forceinline__ void ldsm4(uint32_t& r0, uint32_t& r1, uint32_t& r2, uint32_t& r3, uint32_t a) {
    asm volatile("ldmatrix.sync.aligned.m8n8.x4.shared.b16 {%0,%1,%2,%3}, [%4];\n"
                 : "=r"(r0), "=r"(r1), "=r"(r2), "=r"(r3) : "r"(a));
}
__device__ __forceinline__ void mma16816(float* c, uint32_t a0, uint32_t a1, uint32_t a2, uint32_t a3,
                                         uint32_t b0, uint32_t b1) {
    asm volatile(
        "mma.sync.aligned.m16n8k16.row.col.f32.f16.f16.f32 "
        "{%0,%1,%2,%3}, {%4,%5,%6,%7}, {%8,%9}, {%0,%1,%2,%3};\n"
        : "+f"(c[0]), "+f"(c[1]), "+f"(c[2]), "+f"(c[3])
        : "r"(a0), "r"(a1), "r"(a2), "r"(a3), "r"(b0), "r"(b1));
}

template <int MM, int NN, int KK, int WHICH>
__global__ void __launch_bounds__(256, 2) gemm_hmma(float* __restrict__ outp) {
    const __half* __restrict__ A = (WHICH == 1) ? g_A  : g_Z;
    const __half* __restrict__ B = (WHICH == 1) ? g_Wf : g_Wi;

    constexpr int FBM = 128, FBN = 128, FBK = 32;
    constexpr int LDT = FBK + 8;
    __shared__ __align__(16) __half As[2][FBM * LDT];
    __shared__ __align__(16) __half Bs[2][FBN * LDT];

    const int tid = threadIdx.x, lane = tid & 31, wid = tid >> 5;
    const int wm = wid & 3, wn = wid >> 2;
    const int bm = blockIdx.y * FBM, bn = blockIdx.x * FBN;

    float acc[2][8][4];
#pragma unroll
    for (int i = 0; i < 2; i++)
#pragma unroll
        for (int j = 0; j < 8; j++)
#pragma unroll
            for (int q = 0; q < 4; q++) acc[i][j][q] = 0.f;

    const int trow = tid >> 2, tcol = (tid & 3) << 3;
    auto load_tile = [&](int kt, int buf) {
        const int k0 = kt * FBK;
        const __half* ag = A + (size_t)(bm + trow) * KK + k0 + tcol;
        cp16(smem_u32(&As[buf][trow * LDT + tcol]), ag);
        cp16(smem_u32(&As[buf][(trow + 64) * LDT + tcol]), ag + (size_t)64 * KK);
        const __half* bg = B + (size_t)(bn + trow) * KK + k0 + tcol;
        cp16(smem_u32(&Bs[buf][trow * LDT + tcol]), bg);
        cp16(smem_u32(&Bs[buf][(trow + 64) * LDT + tcol]), bg + (size_t)64 * KK);
        cp_commit();
    };

    load_tile(0, 0);
    constexpr int KT = KK / FBK;
    for (int kt = 0; kt < KT; kt++) {
        const int buf = kt & 1;
        if (kt + 1 < KT) { load_tile(kt + 1, buf ^ 1); cp_wait<1>(); }
        else            { cp_wait<0>(); }
        __syncthreads();
#pragma unroll
        for (int ks = 0; ks < 2; ks++) {
            uint32_t a[2][4], b[4][4];
#pragma unroll
            for (int mt = 0; mt < 2; mt++) {
                int r = wm * 32 + mt * 16 + (lane & 15);
                int c = ks * 16 + ((lane >> 4) << 3);
                ldsm4(a[mt][0], a[mt][1], a[mt][2], a[mt][3], smem_u32(&As[buf][r * LDT + c]));
            }
#pragma unroll
            for (int nt = 0; nt < 4; nt++) {
                int r = wn * 64 + nt * 16 + (lane & 15);
                int c = ks * 16 + ((lane >> 4) << 3);
                ldsm4(b[nt][0], b[nt][1], b[nt][2], b[nt][3], smem_u32(&Bs[buf][r * LDT + c]));
            }
#pragma unroll
            for (int mt = 0; mt < 2; mt++)
#pragma unroll
                for (int nt = 0; nt < 8; nt++)
                    mma16816(acc[mt][nt], a[mt][0], a[mt][1], a[mt][2], a[mt][3],
                             b[nt >> 1][nt & 1], b[nt >> 1][(nt & 1) + 2]);
        }
        __syncthreads();
    }
#pragma unroll
    for (int mt = 0; mt < 2; mt++)
#pragma unroll
        for (int nt = 0; nt < 8; nt++) {
            int row = bm + wm * 32 + mt * 16 + (lane >> 2);
            int col = bn + wn * 64 + nt * 8 + ((lane & 3) << 1);
            if (WHICH == 1) {
                g_X[(size_t)row * NN + col]           = __float2half_rn(acc[mt][nt][0]);
                g_X[(size_t)row * NN + col + 1]       = __float2half_rn(acc[mt][nt][1]);
                g_X[(size_t)(row + 8) * NN + col]     = __float2half_rn(acc[mt][nt][2]);
                g_X[(size_t)(row + 8) * NN + col + 1] = __float2half_rn(acc[mt][nt][3]);
            } else {
                outp[(size_t)row * NN + col]           = acc[mt][nt][0];
                outp[(size_t)row * NN + col + 1]       = acc[mt][nt][1];
                outp[(size_t)(row + 8) * NN + col]     = acc[mt][nt][2];
                outp[(size_t)(row + 8) * NN + col + 1] = acc[mt][nt][3];
            }
        }
}

// ---------------- host: tensor-map encoding via dlopen ------------------------
typedef CUresult (*EncodeFn)(CUtensorMap*, CUtensorMapDataType, cuuint32_t, void*,
                             const cuuint64_t*, const cuuint64_t*, const cuuint32_t*,
                             const cuuint32_t*, CUtensorMapInterleave, CUtensorMapSwizzle,
                             CUtensorMapL2promotion, CUtensorMapFloatOOBfill);
static EncodeFn get_encoder() {
    static EncodeFn fn = nullptr;
    static bool tried = false;
    if (!tried) {
        tried = true;
        void* h = dlopen("libcuda.so.1", RTLD_LAZY | RTLD_GLOBAL);
        if (!h) h = dlopen("libcuda.so", RTLD_LAZY | RTLD_GLOBAL);
        if (h) fn = (EncodeFn)dlsym(h, "cuTensorMapEncodeTiled");
    }
    return fn;
}
// fp16 [rows, cols] row-major, box [64 x 128 x 1], SW128
static bool encode_tm(CUtensorMap* tm, void* base, uint64_t rows, uint64_t cols) {
    EncodeFn fn = get_encoder();
    if (!fn || !base) return false;
    cuuint64_t dims[3]    = {cols, rows, 1};
    cuuint64_t strides[2] = {cols * 2, cols * rows * 2};
    cuuint32_t box[3]     = {64, 128, 1};
    cuuint32_t es[3]      = {1, 1, 1};
    return fn(tm, CU_TENSOR_MAP_DATA_TYPE_FLOAT16, 3, base, dims, strides, box, es,
              CU_TENSOR_MAP_INTERLEAVE_NONE, CU_TENSOR_MAP_SWIZZLE_128B,
              CU_TENSOR_MAP_L2_PROMOTION_L2_128B,
              CU_TENSOR_MAP_FLOAT_OOB_FILL_NONE) == CUDA_SUCCESS;
}

// ---------------- launch -------------------------------------------------------
extern "C" void kernel_launch(void* const* d_in, const int* in_sizes, int n_in,
                              void* d_out, int out_size) {
    const float* x = (const float*)d_in[0];
    const float* k = (const float*)d_in[1];
    float* out = (float*)d_out;

    cudaFuncAttributes fa{};
    bool use_tc = (cudaFuncGetAttributes(&fa, (const void*)gemm_tma<K1, 1, 1>) == cudaSuccess)
                  && (fa.numRegs >= 40);

    static CUtensorMap tmWf, tmWi, tmZ;
    static int tm_state = 0;
    if (use_tc && tm_state == 0) {
        void *pWf = nullptr, *pWi = nullptr, *pZ = nullptr;
        cudaGetSymbolAddress(&pWf, g_Wf);
        cudaGetSymbolAddress(&pWi, g_Wi);
        cudaGetSymbolAddress(&pZ,  g_Z);
        bool ok = encode_tm(&tmWf, pWf, N1, K1)
               && encode_tm(&tmWi, pWi, N2, K2)
               && encode_tm(&tmZ,  pZ,  M2, K2);
        tm_state = ok ? 1 : -1;
    }
    if (tm_state != 1) use_tc = false;

    fill_Wf<<<(N1 * K1 / 8) / 256, 256>>>();

    if (use_tc) {
        constexpr int SM1 = StageCfg<1>::SMEM_DYN;   // GEMM1: BNT=1
        constexpr int SM2 = StageCfg<2>::SMEM_DYN;   // GEMM2: BNT=2
        cudaFuncSetAttribute((const void*)gemm_tma<K1, 1, 1>,
                             cudaFuncAttributeMaxDynamicSharedMemorySize, SM1);
        cudaFuncSetAttribute((const void*)gemm_tma<K2, 2, 2>,
                             cudaFuncAttributeMaxDynamicSharedMemorySize, SM2);
        // GEMM1: N-tile 256 -> 4 bn x 27 m = 108 clusters
        gemm_tma<K1, 1, 1><<<dim3(2 * (N1 / 256), M1 / 256), 256, SM1>>>(x, k, nullptr, tmWf, tmWf);
        mid_pointwise_fillwi<<<PW_BLOCKS + (N2 * K2 / 8) / 256, 256>>>();
        // GEMM2: N-tile 512 -> 8 bn x 24 m = 192 clusters
        gemm_tma<K2, 2, 2><<<dim3(2 * (N2 / 512), M2 / 256), 256, SM2>>>(x, k, out, tmZ, tmWi);
    } else {
        convert_inputs<<<(M1 * K1 / 2) / 256, 256>>>((const float2*)x, (const float2*)k);
        gemm_hmma<M1, N1, K1, 1><<<dim3(N1 / 128, M1 / 128), 256>>>(nullptr);
        mid_pointwise_fillwi<<<PW_BLOCKS + (N2 * K2 / 8) / 256, 256>>>();
        gemm_hmma<M2, N2, K2, 2><<<dim3(N2 / 128, M2 / 128), 256>>>(out);
    }
}

// round 9
// speedup vs baseline: 1.3657x; 1.3657x over previous
#include <cuda_runtime.h>
#include <cuda.h>
#include <cuda_fp16.h>
#include <math.h>
#include <stdint.h>
#include <dlfcn.h>

// ---------------- problem constants -----------------------------------------
#define LSEQ  4096
#define NFFT  8192
#define NBINS 512
#define BH    6144         // B*H
#define HDIM  768
#define M1    6912         // BH + HDIM (k rows ride along in GEMM1)
#define K1    4096
#define N1    1024         // 512 bins x (re, im)
#define M2    6144
#define K2    1024
#define N2    4096
#define NCLUSTERS 74

// sm_103a feature pass? (tcgen05/TMEM only exist in arch-specific compile)
#if defined(__CUDA_ARCH__) && (__CUDA_ARCH__ >= 1000) && \
    (defined(__CUDA_ARCH_FEAT_SM103_ALL) || defined(__CUDA_ARCH_SPECIFIC__) || \
     defined(__CUDA_ARCH_FAMILY_SPECIFIC__))
#define HAS_TCGEN05 1
#else
#define HAS_TCGEN05 0
#endif

// ---------------- device scratch (no allocs allowed) ------------------------
__device__ __align__(16) __half g_A [(size_t)M1 * K1];   // [M1,K1] fp16 inputs [x;k]
__device__ __align__(16) __half g_Wf[(size_t)N1 * K1];   // [N1,K1] fwd DFT weights (K-major)
__device__ __align__(16) __half g_X [(size_t)M1 * N1];   // spectra, fp16
__device__ __align__(16) __half g_Z [(size_t)M2 * K2];   // scaled product spectrum
__device__ __align__(16) __half g_Wi[(size_t)N2 * K2];   // [N2,K2] inv DFT weights (K-major)

// ---------------- generic PTX helpers ----------------------------------------
__device__ __forceinline__ uint32_t smem_u32(const void* p) {
    return (uint32_t)__cvta_generic_to_shared(p);
}
__device__ __forceinline__ void cp16(uint32_t dst, const void* src) {
    asm volatile("cp.async.cg.shared.global [%0], [%1], 16;\n" :: "r"(dst), "l"(src));
}
__device__ __forceinline__ void cp_commit() {
    asm volatile("cp.async.commit_group;\n" ::: "memory");
}
template <int N>
__device__ __forceinline__ void cp_wait() {
    asm volatile("cp.async.wait_group %0;\n" :: "n"(N) : "memory");
}
__device__ __forceinline__ uint32_t cluster_rank() {
    uint32_t r; asm("mov.u32 %0, %%cluster_ctarank;" : "=r"(r)); return r;
}

#define MBARRIER_INIT(mbar, count) \
    asm volatile("mbarrier.init.shared.b64 [%0], %1;" :: "r"((uint32_t)(mbar)), "r"((uint32_t)(count)) : "memory")
#define MBARRIER_ARRIVE_LEADER(mbar) \
    asm volatile("{\n\t.reg .b32 la;\n\t" \
        "and.b32 la, %0, 0xFEFFFFFF;\n\t" \
        "mbarrier.arrive.shared::cluster.b64 _, [la];\n\t}" \
        :: "r"((uint32_t)(mbar)) : "memory")
#define MBARRIER_EXPECT_TX(mbar, bytes) \
    asm volatile("mbarrier.arrive.expect_tx.shared.b64 _, [%0], %1;" \
                 :: "r"((uint32_t)(mbar)), "r"((uint32_t)(bytes)) : "memory")
#define MBARRIER_WAIT_PARITY(mbar, parity) do {                                   \
    uint32_t _m = (uint32_t)(mbar); uint32_t _p = (uint32_t)(parity); uint32_t _d; \
    asm volatile("{\n\t.reg .pred p;\n\t"                                         \
        "mbarrier.try_wait.parity.acquire.cta.shared::cta.b64 p, [%1], %2;\n\t"   \
        "selp.b32 %0, 1, 0, p;\n\t}"                                              \
        : "=r"(_d) : "r"(_m), "r"(_p) : "memory");                                \
    if (!_d) {                                                                    \
        asm volatile("{\n\t.reg .pred P1;\n\t"                                    \
            "WL_%=:\n\t"                                                          \
            "mbarrier.try_wait.parity.acquire.cta.shared::cta.b64 P1, [%0], %1, 0x989680;\n\t" \
            "@P1 bra.uni WD_%=;\n\t"                                              \
            "bra.uni WL_%=;\n\t"                                                  \
            "WD_%=:\n\t}" :: "r"(_m), "r"(_p) : "memory");                        \
    } } while (0)
#define CLUSTER_SYNC() do { \
    asm volatile("barrier.cluster.arrive.aligned;" ::: "memory"); \
    asm volatile("barrier.cluster.wait.aligned;" ::: "memory"); } while (0)

// ---------------- setup kernels ----------------------------------------------
#define TWO_PI_OVER_N 7.6699039e-4f   // 2*pi/8192

// Fused pre kernel: convert inputs to fp16 g_A (8 elems/thread) + fill Wf.
#define CV_BLOCKS 13824   // M1*K1/8/256
__global__ void pre_convert_fillwf(const float4* __restrict__ x4, const float4* __restrict__ k4) {
    if (blockIdx.x < CV_BLOCKS) {
        size_t i = ((size_t)blockIdx.x * 256 + threadIdx.x) * 2;   // float4 index (8 floats)
        const size_t XN4 = (size_t)BH * LSEQ / 4;
        float4 v0, v1;
        if (i < XN4) { v0 = x4[i]; v1 = x4[i + 1]; }
        else         { v0 = k4[i - XN4]; v1 = k4[i - XN4 + 1]; }
        uint4 u;
        __half2* hp = (__half2*)&u;
        hp[0] = __floats2half2_rn(v0.x, v0.y);
        hp[1] = __floats2half2_rn(v0.z, v0.w);
        hp[2] = __floats2half2_rn(v1.x, v1.y);
        hp[3] = __floats2half2_rn(v1.z, v1.w);
        ((uint4*)g_A)[i >> 1] = u;
    } else {
        int idx = (blockIdx.x - CV_BLOCKS) * 256 + threadIdx.x;   // N1*K1/8 threads
        int n = idx >> 9, c = (idx & 511) << 3;
        int f = n >> 1, odd = n & 1;
        __half h[8];
#pragma unroll
        for (int j = 0; j < 8; j++) {
            int m = (f * (c + j)) & (NFFT - 1);
            float sv, cv;
            __sincosf((float)m * TWO_PI_OVER_N, &sv, &cv);
            h[j] = __float2half_rn(odd ? -sv : cv);
        }
        *(uint4*)(g_Wf + (size_t)n * K1 + c) = *(uint4*)h;
    }
}

// Fused middle kernel: pointwise Z + fill Wi
#define PW_BLOCKS 3072
__global__ void mid_pointwise_fillwi() {
    if (blockIdx.x < PW_BLOCKS) {
        int idx = blockIdx.x * 256 + threadIdx.x;   // BH*NBINS/4 threads
        int r = idx >> 7, f4 = (idx & 127) << 2;
        int h = r % HDIM;
        uint4 xu = *(const uint4*)(g_X + (size_t)r * N1 + 2 * f4);
        uint4 ku = *(const uint4*)(g_X + (size_t)(BH + h) * N1 + 2 * f4);
        const __half2* xh = (const __half2*)&xu;
        const __half2* kh = (const __half2*)&ku;
        uint4 zu;
        __half2* zh = (__half2*)&zu;
#pragma unroll
        for (int j = 0; j < 4; j++) {
            float2 X = __half22float2(xh[j]);
            float2 K = __half22float2(kh[j]);
            float alpha = ((f4 + j) == 0) ? (1.0f / 8192.0f) : (2.0f / 8192.0f);
            float Zr = alpha * (X.x * K.x - X.y * K.y);
            float Zi = alpha * (X.x * K.y + X.y * K.x);
            zh[j] = __floats2half2_rn(Zr, -Zi);
        }
        *(uint4*)(g_Z + (size_t)r * K2 + 2 * f4) = zu;
    } else {
        int idx = (blockIdx.x - PW_BLOCKS) * 256 + threadIdx.x;  // N2*K2/8 threads
        int n = idx >> 7, c = (idx & 127) << 3;
        __half h[8];
#pragma unroll
        for (int j = 0; j < 4; j++) {
            int f = (c >> 1) + j;
            int m = (f * n) & (NFFT - 1);
            float sv, cv;
            __sincosf((float)m * TWO_PI_OVER_N, &sv, &cv);
            h[2 * j]     = __float2half_rn(cv);
            h[2 * j + 1] = __float2half_rn(sv);
        }
        *(uint4*)(g_Wi + (size_t)n * K2 + c) = *(uint4*)h;
    }
}

// ================= persistent tcgen05 cg2 + TMA path (sm_103a) ===============
// C[M,N] = A[M,K] @ B[N,K]^T.  74 persistent clusters x 2 CTAs.
// Per cluster-tile: M=256 (128 rows/CTA), N=512 (two cg2 N=256 MMAs).
// BK=64, 4-stage TMA ring running continuously across tiles.
// Roles per CTA: warps 0-3 epilogue, warp6 lane0 TMA producer,
// warp7 lane0 (rank0) MMA issuer.
constexpr int STG = 4, BK = 64;
constexpr int BLK16K = 16384;
constexpr int STAGE_B = 3 * BLK16K;                    // A + 2 B groups = 48 KB
constexpr int SMEM_DYN = 2048 + STG * STAGE_B;         // ~194 KB

#if HAS_TCGEN05
static constexpr uint64_t SMEM_DESC_BASE_SW128 =
    (uint64_t(2) << 61) | (uint64_t(1) << 46) | (uint64_t(64) << 32) | (uint64_t(1) << 16);
#define MAKE_SMEM_DESC(addr) (SMEM_DESC_BASE_SW128 | ((uint64_t)((addr) >> 4) & 0x3FFF))

#define TCGEN05_ALLOC_CG2(smem_addr, ncols) \
    asm volatile("tcgen05.alloc.cta_group::2.sync.aligned.shared::cta.b32 [%0], %1;" \
                 :: "r"((uint32_t)(smem_addr)), "r"((uint32_t)(ncols)) : "memory")
#define TCGEN05_DEALLOC_CG2(tmem, ncols) \
    asm volatile("tcgen05.dealloc.cta_group::2.sync.aligned.b32 %0, %1;" :: "r"(tmem), "r"((uint32_t)(ncols)))
#define TCGEN05_RELINQ_CG2() \
    asm volatile("tcgen05.relinquish_alloc_permit.cta_group::2.sync.aligned;")
#define TCGEN05_COMMIT_MC_CG2(mbar, mask) \
    asm volatile("tcgen05.commit.cta_group::2.mbarrier::arrive::one.shared::cluster.multicast::cluster.b64 [%0], %1;" \
                 :: "r"((uint32_t)(mbar)), "h"((uint16_t)(mask)) : "memory")
#define TCGEN05_FENCE_AFTER() asm volatile("tcgen05.fence::after_thread_sync;" ::: "memory")
#define TCGEN05_WAIT_LD()     asm volatile("tcgen05.wait::ld.sync.aligned;" ::: "memory")
#define TCGEN05_LD_X32(r, addr) \
    asm volatile("tcgen05.ld.sync.aligned.32x32b.x32.b32 "                         \
        "{%0, %1, %2, %3, %4, %5, %6, %7, %8, %9, %10, %11, %12, %13, %14, %15, "  \
        " %16, %17, %18, %19, %20, %21, %22, %23, %24, %25, %26, %27, %28, %29, %30, %31}, [%32];" \
        : "=r"((r)[0]),  "=r"((r)[1]),  "=r"((r)[2]),  "=r"((r)[3]),               \
          "=r"((r)[4]),  "=r"((r)[5]),  "=r"((r)[6]),  "=r"((r)[7]),               \
          "=r"((r)[8]),  "=r"((r)[9]),  "=r"((r)[10]), "=r"((r)[11]),              \
          "=r"((r)[12]), "=r"((r)[13]), "=r"((r)[14]), "=r"((r)[15]),              \
          "=r"((r)[16]), "=r"((r)[17]), "=r"((r)[18]), "=r"((r)[19]),              \
          "=r"((r)[20]), "=r"((r)[21]), "=r"((r)[22]), "=r"((r)[23]),              \
          "=r"((r)[24]), "=r"((r)[25]), "=r"((r)[26]), "=r"((r)[27]),              \
          "=r"((r)[28]), "=r"((r)[29]), "=r"((r)[30]), "=r"((r)[31])               \
        : "r"(addr))

// cg2 TMA: both CTAs execute; complete_tx targets the LEADER's barrier (bit 24 cleared)
#define TMA_LOAD_CG2(dst, map, cx, cy, mbar) \
    asm volatile("{\n\t.reg .b32 lb;\n\t" \
        "and.b32 lb, %4, 0xFEFFFFFF;\n\t" \
        "cp.async.bulk.tensor.3d.cta_group::2.shared::cluster.global" \
        ".tile.mbarrier::complete_tx::bytes [%0], [%1, {%2, %3, %5}], [lb];\n\t}" \
        :: "r"((uint32_t)(dst)), "l"(map), "r"((int32_t)(cx)), "r"((int32_t)(cy)), \
           "r"((uint32_t)(mbar)), "r"(0) : "memory")

__device__ __forceinline__ void mma_f16_ss_cg2(uint32_t d, uint64_t ad, uint64_t bd,
                                               uint32_t idesc, uint32_t enable) {
    asm volatile(
        "{\n\t.reg .pred p;\n\t"
        "setp.ne.u32 p, %4, 0;\n\t"
        "tcgen05.mma.cta_group::2.kind::f16 [%0], %1, %2, %3, "
        "{%5, %5, %5, %5, %5, %5, %5, %5}, p;\n\t}"
        :: "r"(d), "l"(ad), "l"(bd), "r"(idesc), "r"(enable), "r"(0u)
        : "memory");
}
#endif // HAS_TCGEN05

// WHICH=1: A=g_A, B=g_Wf, C=g_X fp16 (M1,N1,K1).  WHICH=2: A=g_Z, B=g_Wi, C=outp fp32.
template <int KK, int WHICH>
__global__ void __launch_bounds__(256, 1) __cluster_dims__(2, 1, 1)
gemm_tma(float* __restrict__ outp,
         const __grid_constant__ CUtensorMap tmA, const __grid_constant__ CUtensorMap tmB) {
#if HAS_TCGEN05
    extern __shared__ char smem[];
    constexpr int NN = (WHICH == 1) ? N1 : N2;
    constexpr int MM = (WHICH == 1) ? M1 : M2;
    constexpr int KT = KK / BK;
    constexpr int MT = MM / 256, NT = NN / 512;
    constexpr int NTILES = MT * NT;
    constexpr uint32_t TX = 6 * BLK16K;               // 3 boxes x 2 CTAs per stage

    const uint32_t sb = (smem_u32(smem) + 1023u) & ~1023u;
    const uint32_t mb_full  = sb + 8;    // 4 x 8B (leader's live)
    const uint32_t mb_empty = sb + 40;   // 4 x 8B
    const uint32_t mb_done  = sb + 72;
    const uint32_t mb_free  = sb + 80;
    const uint32_t tb = sb + 1024;

    const int tid = threadIdx.x, wid = tid >> 5, lane = tid & 31;
    const uint32_t rank = cluster_rank();
    const int cid = blockIdx.x >> 1;

    if (tid == 0) {
        for (int s = 0; s < STG; s++) {
            MBARRIER_INIT(mb_full + 8 * s, 1);    // expect_tx arrive only
            MBARRIER_INIT(mb_empty + 8 * s, 1);   // multicast MMA commit
        }
        MBARRIER_INIT(mb_done, 1);                // multicast MMA commit
        MBARRIER_INIT(mb_free, 2);                // one epilogue arrive per CTA
    }
    if (wid == 4) { TCGEN05_ALLOC_CG2(sb, 512); TCGEN05_RELINQ_CG2(); }
    __syncthreads();
    uint32_t tmem;
    asm volatile("ld.shared.b32 %0, [%1];" : "=r"(tmem) : "r"(sb));
    CLUSTER_SYNC();

    if (tid == 192) {
        // ------------------- TMA producer (warp 6 lane 0) ---------------------
        int gs = 0;
        for (int t = cid; t < NTILES; t += NCLUSTERS) {
            const int mt = t % MT, nt = t / MT;
            const int abase = mt * 256 + (int)rank * 128;
            const int bbase = nt * 512 + (int)rank * 128;
            for (int kt = 0; kt < KT; kt++, gs++) {
                const int s = gs & (STG - 1);
                MBARRIER_WAIT_PARITY(mb_empty + 8 * s, ((gs >> 2) + 1) & 1);
                if (rank == 0) MBARRIER_EXPECT_TX(mb_full + 8 * s, TX);
                const int k0 = kt * BK;
                const uint32_t sA = tb + s * STAGE_B;
                TMA_LOAD_CG2(sA, &tmA, k0, abase, mb_full + 8 * s);
                TMA_LOAD_CG2(sA + BLK16K,     &tmB, k0, bbase,       mb_full + 8 * s);
                TMA_LOAD_CG2(sA + 2 * BLK16K, &tmB, k0, bbase + 256, mb_full + 8 * s);
            }
        }
    } else if (rank == 0 && tid == 224) {
        // ------------------- MMA issuer (rank0 warp 7 lane 0) -----------------
        const uint32_t idesc = (1u << 4) | (32u << 17) | (16u << 24);  // F32, N=256, M=256
        int gs = 0, it = 0;
        for (int t = cid; t < NTILES; t += NCLUSTERS, it++) {
            MBARRIER_WAIT_PARITY(mb_free, (it + 1) & 1);   // epilogue of tile it-1 done
            for (int kt = 0; kt < KT; kt++, gs++) {
                const int s = gs & (STG - 1);
                MBARRIER_WAIT_PARITY(mb_full + 8 * s, (gs >> 2) & 1);
                const uint64_t ad = MAKE_SMEM_DESC(tb + s * STAGE_B);
                const uint64_t bd = MAKE_SMEM_DESC(tb + s * STAGE_B + BLK16K);
#pragma unroll
                for (int j = 0; j < 4; j++) {
                    uint32_t en = (uint32_t)((kt | j) != 0);
                    mma_f16_ss_cg2(tmem,       ad + 2 * j, bd + 2 * j,        idesc, en);
                    mma_f16_ss_cg2(tmem + 256, ad + 2 * j, bd + 1024 + 2 * j, idesc, en);
                }
                TCGEN05_COMMIT_MC_CG2(mb_empty + 8 * s, 3);
            }
            TCGEN05_COMMIT_MC_CG2(mb_done, 3);
        }
    } else if (tid < 128) {
        // ------------------- epilogue (warps 0-3) -----------------------------
        int it = 0;
        for (int t = cid; t < NTILES; t += NCLUSTERS, it++) {
            MBARRIER_WAIT_PARITY(mb_done, it & 1);
            TCGEN05_FENCE_AFTER();
            const int mt = t % MT, nt = t / MT;
            const int grow = mt * 256 + (int)rank * 128 + wid * 32 + lane;
#pragma unroll
            for (int c0 = 0; c0 < 512; c0 += 32) {
                uint32_t r[32];
                TCGEN05_LD_X32(r, tmem + c0);
                TCGEN05_WAIT_LD();
                if (WHICH == 1) {
                    uint4 u[2], v[2];
                    __half2* hp = (__half2*)u;
                    __half2* vp = (__half2*)v;
#pragma unroll
                    for (int q = 0; q < 8; q++) {
                        hp[q] = __floats2half2_rn(__uint_as_float(r[2 * q]), __uint_as_float(r[2 * q + 1]));
                        vp[q] = __floats2half2_rn(__uint_as_float(r[16 + 2 * q]), __uint_as_float(r[17 + 2 * q]));
                    }
                    __half* dst = g_X + (size_t)grow * NN + nt * 512 + c0;
                    *(uint4*)(dst)      = u[0];
                    *(uint4*)(dst + 8)  = u[1];
                    *(uint4*)(dst + 16) = v[0];
                    *(uint4*)(dst + 24) = v[1];
                } else {
                    float* dst = outp + (size_t)grow * NN + nt * 512 + c0;
#pragma unroll
                    for (int q = 0; q < 8; q++) {
                        float4 v4 = make_float4(__uint_as_float(r[4 * q + 0]), __uint_as_float(r[4 * q + 1]),
                                                __uint_as_float(r[4 * q + 2]), __uint_as_float(r[4 * q + 3]));
                        *(float4*)(dst + 4 * q) = v4;
                    }
                }
            }
            asm volatile("bar.sync 1, 128;" ::: "memory");
            if (tid == 0) MBARRIER_ARRIVE_LEADER(mb_free);
        }
    }

    __syncthreads();
    if (wid == 4) TCGEN05_DEALLOC_CG2(tmem, 512);
    CLUSTER_SYNC();
#endif // HAS_TCGEN05
}

// ================= HMMA fallback (compiles everywhere) ========================
__device__ __forceinline__ void ldsm4(uint32_t& r0, uint32_t& r1, uint32_t& r2, uint32_t& r3, uint32_t a) {
    asm volatile("ldmatrix.sync.aligned.m8n8.x4.shared.b16 {%0,%1,%2,%3}, [%4];\n"
                 : "=r"(r0), "=r"(r1), "=r"(r2), "=r"(r3) : "r"(a));
}
__device__ __forceinline__ void mma16816(float* c, uint32_t a0, uint32_t a1, uint32_t a2, uint32_t a3,
                                         uint32_t b0, uint32_t b1) {
    asm volatile(
        "mma.sync.aligned.m16n8k16.row.col.f32.f16.f16.f32 "
        "{%0,%1,%2,%3}, {%4,%5,%6,%7}, {%8,%9}, {%0,%1,%2,%3};\n"
        : "+f"(c[0]), "+f"(c[1]), "+f"(c[2]), "+f"(c[3])
        : "r"(a0), "r"(a1), "r"(a2), "r"(a3), "r"(b0), "r"(b1));
}

template <int MM, int NN, int KK, int WHICH>
__global__ void __launch_bounds__(256, 2) gemm_hmma(float* __restrict__ outp) {
    const __half* __restrict__ A = (WHICH == 1) ? g_A  : g_Z;
    const __half* __restrict__ B = (WHICH == 1) ? g_Wf : g_Wi;

    constexpr int FBM = 128, FBN = 128, FBK = 32;
    constexpr int LDT = FBK + 8;
    __shared__ __align__(16) __half As[2][FBM * LDT];
    __shared__ __align__(16) __half Bs[2][FBN * LDT];

    const int tid = threadIdx.x, lane = tid & 31, wid = tid >> 5;
    const int wm = wid & 3, wn = wid >> 2;
    const int bm = blockIdx.y * FBM, bn = blockIdx.x * FBN;

    float acc[2][8][4];
#pragma unroll
    for (int i = 0; i < 2; i++)
#pragma unroll
        for (int j = 0; j < 8; j++)
#pragma unroll
            for (int q = 0; q < 4; q++) acc[i][j][q] = 0.f;

    const int trow = tid >> 2, tcol = (tid & 3) << 3;
    auto load_tile = [&](int kt, int buf) {
        const int k0 = kt * FBK;
        const __half* ag = A + (size_t)(bm + trow) * KK + k0 + tcol;
        cp16(smem_u32(&As[buf][trow * LDT + tcol]), ag);
        cp16(smem_u32(&As[buf][(trow + 64) * LDT + tcol]), ag + (size_t)64 * KK);
        const __half* bg = B + (size_t)(bn + trow) * KK + k0 + tcol;
        cp16(smem_u32(&Bs[buf][trow * LDT + tcol]), bg);
        cp16(smem_u32(&Bs[buf][(trow + 64) * LDT + tcol]), bg + (size_t)64 * KK);
        cp_commit();
    };

    load_tile(0, 0);
    constexpr int KT = KK / FBK;
    for (int kt = 0; kt < KT; kt++) {
        const int buf = kt & 1;
        if (kt + 1 < KT) { load_tile(kt + 1, buf ^ 1); cp_wait<1>(); }
        else            { cp_wait<0>(); }
        __syncthreads();
#pragma unroll
        for (int ks = 0; ks < 2; ks++) {
            uint32_t a[2][4], b[4][4];
#pragma unroll
            for (int mt = 0; mt < 2; mt++) {
                int r = wm * 32 + mt * 16 + (lane & 15);
                int c = ks * 16 + ((lane >> 4) << 3);
                ldsm4(a[mt][0], a[mt][1], a[mt][2], a[mt][3], smem_u32(&As[buf][r * LDT + c]));
            }
#pragma unroll
            for (int nt = 0; nt < 4; nt++) {
                int r = wn * 64 + nt * 16 + (lane & 15);
                int c = ks * 16 + ((lane >> 4) << 3);
                ldsm4(b[nt][0], b[nt][1], b[nt][2], b[nt][3], smem_u32(&Bs[buf][r * LDT + c]));
            }
#pragma unroll
            for (int mt = 0; mt < 2; mt++)
#pragma unroll
                for (int nt = 0; nt < 8; nt++)
                    mma16816(acc[mt][nt], a[mt][0], a[mt][1], a[mt][2], a[mt][3],
                             b[nt >> 1][nt & 1], b[nt >> 1][(nt & 1) + 2]);
        }
        __syncthreads();
    }
#pragma unroll
    for (int mt = 0; mt < 2; mt++)
#pragma unroll
        for (int nt = 0; nt < 8; nt++) {
            int row = bm + wm * 32 + mt * 16 + (lane >> 2);
            int col = bn + wn * 64 + nt * 8 + ((lane & 3) << 1);
            if (WHICH == 1) {
                g_X[(size_t)row * NN + col]           = __float2half_rn(acc[mt][nt][0]);
                g_X[(size_t)row * NN + col + 1]       = __float2half_rn(acc[mt][nt][1]);
                g_X[(size_t)(row + 8) * NN + col]     = __float2half_rn(acc[mt][nt][2]);
                g_X[(size_t)(row + 8) * NN + col + 1] = __float2half_rn(acc[mt][nt][3]);
            } else {
                outp[(size_t)row * NN + col]           = acc[mt][nt][0];
                outp[(size_t)row * NN + col + 1]       = acc[mt][nt][1];
                outp[(size_t)(row + 8) * NN + col]     = acc[mt][nt][2];
                outp[(size_t)(row + 8) * NN + col + 1] = acc[mt][nt][3];
            }
        }
}

// ---------------- host: tensor-map encoding via dlopen ------------------------
typedef CUresult (*EncodeFn)(CUtensorMap*, CUtensorMapDataType, cuuint32_t, void*,
                             const cuuint64_t*, const cuuint64_t*, const cuuint32_t*,
                             const cuuint32_t*, CUtensorMapInterleave, CUtensorMapSwizzle,
                             CUtensorMapL2promotion, CUtensorMapFloatOOBfill);
static EncodeFn get_encoder() {
    static EncodeFn fn = nullptr;
    static bool tried = false;
    if (!tried) {
        tried = true;
        void* h = dlopen("libcuda.so.1", RTLD_LAZY | RTLD_GLOBAL);
        if (!h) h = dlopen("libcuda.so", RTLD_LAZY | RTLD_GLOBAL);
        if (h) fn = (EncodeFn)dlsym(h, "cuTensorMapEncodeTiled");
    }
    return fn;
}
// fp16 [rows, cols] row-major, box [64 x 128 x 1], SW128
static bool encode_tm(CUtensorMap* tm, void* base, uint64_t rows, uint64_t cols) {
    EncodeFn fn = get_encoder();
    if (!fn || !base) return false;
    cuuint64_t dims[3]    = {cols, rows, 1};
    cuuint64_t strides[2] = {cols * 2, cols * rows * 2};
    cuuint32_t box[3]     = {64, 128, 1};
    cuuint32_t es[3]      = {1, 1, 1};
    return fn(tm, CU_TENSOR_MAP_DATA_TYPE_FLOAT16, 3, base, dims, strides, box, es,
              CU_TENSOR_MAP_INTERLEAVE_NONE, CU_TENSOR_MAP_SWIZZLE_128B,
              CU_TENSOR_MAP_L2_PROMOTION_L2_128B,
              CU_TENSOR_MAP_FLOAT_OOB_FILL_NONE) == CUDA_SUCCESS;
}

// ---------------- launch -------------------------------------------------------
extern "C" void kernel_launch(void* const* d_in, const int* in_sizes, int n_in,
                              void* d_out, int out_size) {
    const float* x = (const float*)d_in[0];
    const float* k = (const float*)d_in[1];
    float* out = (float*)d_out;

    cudaFuncAttributes fa{};
    bool use_tc = (cudaFuncGetAttributes(&fa, (const void*)gemm_tma<K1, 1>) == cudaSuccess)
                  && (fa.numRegs >= 40);

    static CUtensorMap tmA1, tmB1, tmA2, tmB2;
    static int tm_state = 0;
    if (use_tc && tm_state == 0) {
        void *pA = nullptr, *pWf = nullptr, *pWi = nullptr, *pZ = nullptr;
        cudaGetSymbolAddress(&pA,  g_A);
        cudaGetSymbolAddress(&pWf, g_Wf);
        cudaGetSymbolAddress(&pWi, g_Wi);
        cudaGetSymbolAddress(&pZ,  g_Z);
        bool ok = encode_tm(&tmA1, pA,  M1, K1)
               && encode_tm(&tmB1, pWf, N1, K1)
               && encode_tm(&tmA2, pZ,  M2, K2)
               && encode_tm(&tmB2, pWi, N2, K2);
        tm_state = ok ? 1 : -1;
    }
    if (tm_state != 1) use_tc = false;

    pre_convert_fillwf<<<CV_BLOCKS + (N1 * K1 / 8) / 256, 256>>>(
        (const float4*)x, (const float4*)k);

    if (use_tc) {
        cudaFuncSetAttribute((const void*)gemm_tma<K1, 1>,
                             cudaFuncAttributeMaxDynamicSharedMemorySize, SMEM_DYN);
        cudaFuncSetAttribute((const void*)gemm_tma<K2, 2>,
                             cudaFuncAttributeMaxDynamicSharedMemorySize, SMEM_DYN);
        gemm_tma<K1, 1><<<dim3(2 * NCLUSTERS, 1), 256, SMEM_DYN>>>(nullptr, tmA1, tmB1);
        mid_pointwise_fillwi<<<PW_BLOCKS + (N2 * K2 / 8) / 256, 256>>>();
        gemm_tma<K2, 2><<<dim3(2 * NCLUSTERS, 1), 256, SMEM_DYN>>>(out, tmA2, tmB2);
    } else {
        gemm_hmma<M1, N1, K1, 1><<<dim3(N1 / 128, M1 / 128), 256>>>(nullptr);
        mid_pointwise_fillwi<<<PW_BLOCKS + (N2 * K2 / 8) / 256, 256>>>();
        gemm_hmma<M2, N2, K2, 2><<<dim3(N2 / 128, M2 / 128), 256>>>(out);
    }
}

// round 11
// speedup vs baseline: 1.3888x; 1.0169x over previous
#include <cuda_runtime.h>
#include <cuda.h>
#include <cuda_fp16.h>
#include <math.h>
#include <stdint.h>
#include <dlfcn.h>

// ---------------- problem constants -----------------------------------------
#define LSEQ  4096
#define NFFT  8192
#define NBINS 512
#define BH    6144         // B*H
#define HDIM  768
#define M1    6912         // BH + HDIM (k rows ride along in GEMM1)
#define K1    4096
#define N1    1024         // 512 bins x (re, im)
#define M2    6144
#define K2    1024
#define N2    4096
#define NCL4  33           // persistent 4-CTA clusters (CTAS_ACTIVE[4]=132)

// sm_103a feature pass? (tcgen05/TMEM only exist in arch-specific compile)
#if defined(__CUDA_ARCH__) && (__CUDA_ARCH__ >= 1000) && \
    (defined(__CUDA_ARCH_FEAT_SM103_ALL) || defined(__CUDA_ARCH_SPECIFIC__) || \
     defined(__CUDA_ARCH_FAMILY_SPECIFIC__))
#define HAS_TCGEN05 1
#else
#define HAS_TCGEN05 0
#endif

// ---------------- device scratch (no allocs allowed) ------------------------
__device__ __align__(16) __half g_A [(size_t)M1 * K1];   // [M1,K1] fp16 inputs [x;k]
__device__ __align__(16) __half g_Wf[(size_t)N1 * K1];   // [N1,K1] fwd DFT weights (K-major)
__device__ __align__(16) __half g_X [(size_t)M1 * N1];   // spectra, fp16
__device__ __align__(16) __half g_Z [(size_t)M2 * K2];   // scaled product spectrum
__device__ __align__(16) __half g_Wi[(size_t)N2 * K2];   // [N2,K2] inv DFT weights (K-major)

// ---------------- generic PTX helpers ----------------------------------------
__device__ __forceinline__ uint32_t smem_u32(const void* p) {
    return (uint32_t)__cvta_generic_to_shared(p);
}
__device__ __forceinline__ void cp16(uint32_t dst, const void* src) {
    asm volatile("cp.async.cg.shared.global [%0], [%1], 16;\n" :: "r"(dst), "l"(src));
}
__device__ __forceinline__ void cp_commit() {
    asm volatile("cp.async.commit_group;\n" ::: "memory");
}
template <int N>
__device__ __forceinline__ void cp_wait() {
    asm volatile("cp.async.wait_group %0;\n" :: "n"(N) : "memory");
}
__device__ __forceinline__ uint32_t cluster_rank() {
    uint32_t r; asm("mov.u32 %0, %%cluster_ctarank;" : "=r"(r)); return r;
}

#define MBARRIER_INIT(mbar, count) \
    asm volatile("mbarrier.init.shared.b64 [%0], %1;" :: "r"((uint32_t)(mbar)), "r"((uint32_t)(count)) : "memory")
#define MBARRIER_ARRIVE_LEADER(mbar) \
    asm volatile("{\n\t.reg .b32 la;\n\t" \
        "and.b32 la, %0, 0xFEFFFFFF;\n\t" \
        "mbarrier.arrive.shared::cluster.b64 _, [la];\n\t}" \
        :: "r"((uint32_t)(mbar)) : "memory")
#define MBARRIER_EXPECT_TX(mbar, bytes) \
    asm volatile("mbarrier.arrive.expect_tx.shared.b64 _, [%0], %1;" \
                 :: "r"((uint32_t)(mbar)), "r"((uint32_t)(bytes)) : "memory")
#define MBARRIER_WAIT_PARITY(mbar, parity) do {                                   \
    uint32_t _m = (uint32_t)(mbar); uint32_t _p = (uint32_t)(parity); uint32_t _d; \
    asm volatile("{\n\t.reg .pred p;\n\t"                                         \
        "mbarrier.try_wait.parity.acquire.cta.shared::cta.b64 p, [%1], %2;\n\t"   \
        "selp.b32 %0, 1, 0, p;\n\t}"                                              \
        : "=r"(_d) : "r"(_m), "r"(_p) : "memory");                                \
    if (!_d) {                                                                    \
        asm volatile("{\n\t.reg .pred P1;\n\t"                                    \
            "WL_%=:\n\t"                                                          \
            "mbarrier.try_wait.parity.acquire.cta.shared::cta.b64 P1, [%0], %1, 0x989680;\n\t" \
            "@P1 bra.uni WD_%=;\n\t"                                              \
            "bra.uni WL_%=;\n\t"                                                  \
            "WD_%=:\n\t}" :: "r"(_m), "r"(_p) : "memory");                        \
    } } while (0)
#define CLUSTER_SYNC() do { \
    asm volatile("barrier.cluster.arrive.aligned;" ::: "memory"); \
    asm volatile("barrier.cluster.wait.aligned;" ::: "memory"); } while (0)

// ---------------- setup kernels ----------------------------------------------
#define TWO_PI_OVER_N 7.6699039e-4f   // 2*pi/8192

// Fused pre kernel: convert inputs to fp16 g_A + fill Wf.
#define CV_BLOCKS 13824   // M1*K1/8/256
__global__ void pre_convert_fillwf(const float4* __restrict__ x4, const float4* __restrict__ k4) {
    if (blockIdx.x < CV_BLOCKS) {
        size_t i = ((size_t)blockIdx.x * 256 + threadIdx.x) * 2;
        const size_t XN4 = (size_t)BH * LSEQ / 4;
        float4 v0, v1;
        if (i < XN4) { v0 = x4[i]; v1 = x4[i + 1]; }
        else         { v0 = k4[i - XN4]; v1 = k4[i - XN4 + 1]; }
        uint4 u;
        __half2* hp = (__half2*)&u;
        hp[0] = __floats2half2_rn(v0.x, v0.y);
        hp[1] = __floats2half2_rn(v0.z, v0.w);
        hp[2] = __floats2half2_rn(v1.x, v1.y);
        hp[3] = __floats2half2_rn(v1.z, v1.w);
        ((uint4*)g_A)[i >> 1] = u;
    } else {
        int idx = (blockIdx.x - CV_BLOCKS) * 256 + threadIdx.x;
        int n = idx >> 9, c = (idx & 511) << 3;
        int f = n >> 1, odd = n & 1;
        __half h[8];
#pragma unroll
        for (int j = 0; j < 8; j++) {
            int m = (f * (c + j)) & (NFFT - 1);
            float sv, cv;
            __sincosf((float)m * TWO_PI_OVER_N, &sv, &cv);
            h[j] = __float2half_rn(odd ? -sv : cv);
        }
        *(uint4*)(g_Wf + (size_t)n * K1 + c) = *(uint4*)h;
    }
}

// Fused middle kernel: pointwise Z + fill Wi
#define PW_BLOCKS 3072
__global__ void mid_pointwise_fillwi() {
    if (blockIdx.x < PW_BLOCKS) {
        int idx = blockIdx.x * 256 + threadIdx.x;
        int r = idx >> 7, f4 = (idx & 127) << 2;
        int h = r % HDIM;
        uint4 xu = *(const uint4*)(g_X + (size_t)r * N1 + 2 * f4);
        uint4 ku = *(const uint4*)(g_X + (size_t)(BH + h) * N1 + 2 * f4);
        const __half2* xh = (const __half2*)&xu;
        const __half2* kh = (const __half2*)&ku;
        uint4 zu;
        __half2* zh = (__half2*)&zu;
#pragma unroll
        for (int j = 0; j < 4; j++) {
            float2 X = __half22float2(xh[j]);
            float2 K = __half22float2(kh[j]);
            float alpha = ((f4 + j) == 0) ? (1.0f / 8192.0f) : (2.0f / 8192.0f);
            float Zr = alpha * (X.x * K.x - X.y * K.y);
            float Zi = alpha * (X.x * K.y + X.y * K.x);
            zh[j] = __floats2half2_rn(Zr, -Zi);
        }
        *(uint4*)(g_Z + (size_t)r * K2 + 2 * f4) = zu;
    } else {
        int idx = (blockIdx.x - PW_BLOCKS) * 256 + threadIdx.x;
        int n = idx >> 7, c = (idx & 127) << 3;
        __half h[8];
#pragma unroll
        for (int j = 0; j < 4; j++) {
            int f = (c >> 1) + j;
            int m = (f * n) & (NFFT - 1);
            float sv, cv;
            __sincosf((float)m * TWO_PI_OVER_N, &sv, &cv);
            h[2 * j]     = __float2half_rn(cv);
            h[2 * j + 1] = __float2half_rn(sv);
        }
        *(uint4*)(g_Wi + (size_t)n * K2 + c) = *(uint4*)h;
    }
}

// ============ persistent 4-CTA-cluster tcgen05 + TMA-multicast path ==========
// Cluster = 2 cg2 pairs {0,1},{2,3}. Super-tile = 2 M-tiles (one per pair) x
// one N=512 tile sharing B. A: cg2 TMA -> pair leader barrier. B: each CTA
// issues ONE 16KB box, multicast across {0,2} (rinp=0) or {1,3} (rinp=1).
// Odd CTAs forward their local B completion to the pair leader.
// DEADLOCK FIX vs R10: mb_empty is CLUSTER-WIDE — each pair issuer commits
// empty[s] with mask 0x0F and every empty has count 2, so producers can never
// overwrite / send tx for a slot the other pair hasn't consumed (no phase
// credit theft).
constexpr int STG = 4, BK = 64;
constexpr int BLK16K = 16384;
constexpr int STAGE_B = 3 * BLK16K;                    // A + Bg0 + Bg1 = 48 KB
constexpr int SMEM_DYN = 2048 + STG * STAGE_B;

#if HAS_TCGEN05
static constexpr uint64_t SMEM_DESC_BASE_SW128 =
    (uint64_t(2) << 61) | (uint64_t(1) << 46) | (uint64_t(64) << 32) | (uint64_t(1) << 16);
#define MAKE_SMEM_DESC(addr) (SMEM_DESC_BASE_SW128 | ((uint64_t)((addr) >> 4) & 0x3FFF))

#define TCGEN05_ALLOC_CG2(smem_addr, ncols) \
    asm volatile("tcgen05.alloc.cta_group::2.sync.aligned.shared::cta.b32 [%0], %1;" \
                 :: "r"((uint32_t)(smem_addr)), "r"((uint32_t)(ncols)) : "memory")
#define TCGEN05_DEALLOC_CG2(tmem, ncols) \
    asm volatile("tcgen05.dealloc.cta_group::2.sync.aligned.b32 %0, %1;" :: "r"(tmem), "r"((uint32_t)(ncols)))
#define TCGEN05_RELINQ_CG2() \
    asm volatile("tcgen05.relinquish_alloc_permit.cta_group::2.sync.aligned;")
#define TCGEN05_COMMIT_MC_CG2(mbar, mask) \
    asm volatile("tcgen05.commit.cta_group::2.mbarrier::arrive::one.shared::cluster.multicast::cluster.b64 [%0], %1;" \
                 :: "r"((uint32_t)(mbar)), "h"((uint16_t)(mask)) : "memory")
#define TCGEN05_FENCE_AFTER() asm volatile("tcgen05.fence::after_thread_sync;" ::: "memory")
#define TCGEN05_WAIT_LD()     asm volatile("tcgen05.wait::ld.sync.aligned;" ::: "memory")
#define TCGEN05_LD_X32(r, addr) \
    asm volatile("tcgen05.ld.sync.aligned.32x32b.x32.b32 "                         \
        "{%0, %1, %2, %3, %4, %5, %6, %7, %8, %9, %10, %11, %12, %13, %14, %15, "  \
        " %16, %17, %18, %19, %20, %21, %22, %23, %24, %25, %26, %27, %28, %29, %30, %31}, [%32];" \
        : "=r"((r)[0]),  "=r"((r)[1]),  "=r"((r)[2]),  "=r"((r)[3]),               \
          "=r"((r)[4]),  "=r"((r)[5]),  "=r"((r)[6]),  "=r"((r)[7]),               \
          "=r"((r)[8]),  "=r"((r)[9]),  "=r"((r)[10]), "=r"((r)[11]),              \
          "=r"((r)[12]), "=r"((r)[13]), "=r"((r)[14]), "=r"((r)[15]),              \
          "=r"((r)[16]), "=r"((r)[17]), "=r"((r)[18]), "=r"((r)[19]),              \
          "=r"((r)[20]), "=r"((r)[21]), "=r"((r)[22]), "=r"((r)[23]),              \
          "=r"((r)[24]), "=r"((r)[25]), "=r"((r)[26]), "=r"((r)[27]),              \
          "=r"((r)[28]), "=r"((r)[29]), "=r"((r)[30]), "=r"((r)[31])               \
        : "r"(addr))

// cg2 TMA: both CTAs of a pair execute; complete_tx to pair-leader barrier
#define TMA_LOAD_CG2(dst, map, cx, cy, mbar) \
    asm volatile("{\n\t.reg .b32 lb;\n\t" \
        "and.b32 lb, %4, 0xFEFFFFFF;\n\t" \
        "cp.async.bulk.tensor.3d.cta_group::2.shared::cluster.global" \
        ".tile.mbarrier::complete_tx::bytes [%0], [%1, {%2, %3, %5}], [lb];\n\t}" \
        :: "r"((uint32_t)(dst)), "l"(map), "r"((int32_t)(cx)), "r"((int32_t)(cy)), \
           "r"((uint32_t)(mbar)), "r"(0) : "memory")

// multicast TMA: data + complete_tx to same offsets in every CTA in mask
#define TMA_LOAD_MC(dst, map, cx, cy, mbar, mask) \
    asm volatile("cp.async.bulk.tensor.3d.shared::cluster.global.tile" \
        ".mbarrier::complete_tx::bytes.multicast::cluster " \
        "[%0], [%1, {%2, %3, %4}], [%5], %6;" \
        :: "r"((uint32_t)(dst)), "l"(map), "r"((int32_t)(cx)), "r"((int32_t)(cy)), \
           "r"(0), "r"((uint32_t)(mbar)), "h"((uint16_t)(mask)) : "memory")

__device__ __forceinline__ void mma_f16_ss_cg2(uint32_t d, uint64_t ad, uint64_t bd,
                                               uint32_t idesc, uint32_t enable) {
    asm volatile(
        "{\n\t.reg .pred p;\n\t"
        "setp.ne.u32 p, %4, 0;\n\t"
        "tcgen05.mma.cta_group::2.kind::f16 [%0], %1, %2, %3, "
        "{%5, %5, %5, %5, %5, %5, %5, %5}, p;\n\t}"
        :: "r"(d), "l"(ad), "l"(bd), "r"(idesc), "r"(enable), "r"(0u)
        : "memory");
}
#endif // HAS_TCGEN05

// WHICH=1: A=g_A, B=g_Wf, C=g_X fp16 (M1,N1,K1).  WHICH=2: A=g_Z, B=g_Wi, C=outp fp32.
template <int KK, int WHICH>
__global__ void __launch_bounds__(256, 1) __cluster_dims__(4, 1, 1)
gemm_tma4(float* __restrict__ outp,
          const __grid_constant__ CUtensorMap tmA, const __grid_constant__ CUtensorMap tmB) {
#if HAS_TCGEN05
    extern __shared__ char smem[];
    constexpr int NN = (WHICH == 1) ? N1 : N2;
    constexpr int MM = (WHICH == 1) ? M1 : M2;
    constexpr int KT = KK / BK;
    constexpr int MT = MM / 256;
    constexpr int MSUP = (MT + 1) / 2;
    constexpr int NTn = NN / 512;
    constexpr int NSUPER = MSUP * NTn;

    const uint32_t sb = (smem_u32(smem) + 1023u) & ~1023u;
    const uint32_t mb_full  = sb + 8;    // 4 x 8B (leaders: pipeline; odd: local B)
    const uint32_t mb_empty = sb + 40;   // 4 x 8B, CLUSTER-WIDE (count 2)
    const uint32_t mb_done  = sb + 72;
    const uint32_t mb_free  = sb + 80;
    const uint32_t tb = sb + 1024;

    const int tid = threadIdx.x, wid = tid >> 5, lane = tid & 31;
    const uint32_t rank = cluster_rank();
    const int pair = (int)(rank >> 1), rinp = (int)(rank & 1);
    const int cid = blockIdx.x >> 2;
    const uint16_t bmask  = rinp ? 0x0A : 0x05;          // B multicast targets
    const uint16_t pmask  = pair ? 0x0C : 0x03;          // pair mask for done commit

    if (tid == 0) {
        for (int s = 0; s < STG; s++) {
            MBARRIER_INIT(mb_full + 8 * s, rinp ? 1 : 2);  // leader: expect+forwarder
            MBARRIER_INIT(mb_empty + 8 * s, 2);            // BOTH pair issuers commit
        }
        MBARRIER_INIT(mb_done, 1);
        MBARRIER_INIT(mb_free, 2);
    }
    if (wid == 4) { TCGEN05_ALLOC_CG2(sb, 512); TCGEN05_RELINQ_CG2(); }
    __syncthreads();
    uint32_t tmem;
    asm volatile("ld.shared.b32 %0, [%1];" : "=r"(tmem) : "r"(sb));
    CLUSTER_SYNC();

    if (tid == 192) {
        // ---------------- TMA producer (warp 6 lane 0, every CTA) -------------
        int gs = 0;
        for (int t = cid; t < NSUPER; t += NCL4) {
            const int nt = t % NTn, msup = t / NTn;
            int mt = msup * 2 + pair; if (mt >= MT) mt = MT - 1;
            const int arow = mt * 256 + rinp * 128;
            const int brow = nt * 512 + pair * 256 + rinp * 128;  // the box we issue
            for (int kt = 0; kt < KT; kt++, gs++) {
                const int s = gs & (STG - 1);
                MBARRIER_WAIT_PARITY(mb_empty + 8 * s, ((gs >> 2) + 1) & 1);
                MBARRIER_EXPECT_TX(mb_full + 8 * s, rinp ? 32768u : 65536u);
                const int k0 = kt * BK;
                const uint32_t sA = tb + s * STAGE_B;
                TMA_LOAD_CG2(sA, &tmA, k0, arow, mb_full + 8 * s);
                TMA_LOAD_MC(sA + BLK16K + pair * BLK16K, &tmB, k0, brow,
                            mb_full + 8 * s, bmask);
            }
        }
    } else if (rinp == 1 && tid == 160) {
        // ---------------- B forwarder (odd CTAs, warp 5 lane 0) ---------------
        int gs = 0;
        for (int t = cid; t < NSUPER; t += NCL4)
            for (int kt = 0; kt < KT; kt++, gs++) {
                const int s = gs & (STG - 1);
                MBARRIER_WAIT_PARITY(mb_full + 8 * s, (gs >> 2) & 1);
                MBARRIER_ARRIVE_LEADER(mb_full + 8 * s);
            }
    } else if (rinp == 0 && tid == 224) {
        // ---------------- MMA issuer (pair leaders, warp 7 lane 0) ------------
        const uint32_t idesc = (1u << 4) | (32u << 17) | (16u << 24);  // F32, N=256, M=256
        int gs = 0, it = 0;
        for (int t = cid; t < NSUPER; t += NCL4, it++) {
            MBARRIER_WAIT_PARITY(mb_free, (it + 1) & 1);
            for (int kt = 0; kt < KT; kt++, gs++) {
                const int s = gs & (STG - 1);
                MBARRIER_WAIT_PARITY(mb_full + 8 * s, (gs >> 2) & 1);
                const uint64_t ad = MAKE_SMEM_DESC(tb + s * STAGE_B);
                const uint64_t bd = MAKE_SMEM_DESC(tb + s * STAGE_B + BLK16K);
#pragma unroll
                for (int j = 0; j < 4; j++) {
                    uint32_t en = (uint32_t)((kt | j) != 0);
                    mma_f16_ss_cg2(tmem,       ad + 2 * j, bd + 2 * j,        idesc, en);
                    mma_f16_ss_cg2(tmem + 256, ad + 2 * j, bd + 1024 + 2 * j, idesc, en);
                }
                TCGEN05_COMMIT_MC_CG2(mb_empty + 8 * s, 0x0F);   // cluster-wide empty
            }
            TCGEN05_COMMIT_MC_CG2(mb_done, pmask);
        }
    } else if (tid < 128) {
        // ---------------- epilogue (warps 0-3, every CTA) ---------------------
        int it = 0;
        for (int t = cid; t < NSUPER; t += NCL4, it++) {
            MBARRIER_WAIT_PARITY(mb_done, it & 1);
            TCGEN05_FENCE_AFTER();
            const int nt = t % NTn, msup = t / NTn;
            const int mtr = msup * 2 + pair;
            const bool skip = (mtr >= MT);                 // dup tile: pair1 skips store
            const int mt = skip ? MT - 1 : mtr;
            const int grow = mt * 256 + rinp * 128 + wid * 32 + lane;
            if (!skip) {
#pragma unroll
                for (int c0 = 0; c0 < 512; c0 += 32) {
                    uint32_t r[32];
                    TCGEN05_LD_X32(r, tmem + c0);
                    TCGEN05_WAIT_LD();
                    if (WHICH == 1) {
                        uint4 u[2], v[2];
                        __half2* hp = (__half2*)u;
                        __half2* vp = (__half2*)v;
#pragma unroll
                        for (int q = 0; q < 8; q++) {
                            hp[q] = __floats2half2_rn(__uint_as_float(r[2 * q]), __uint_as_float(r[2 * q + 1]));
                            vp[q] = __floats2half2_rn(__uint_as_float(r[16 + 2 * q]), __uint_as_float(r[17 + 2 * q]));
                        }
                        __half* dst = g_X + (size_t)grow * NN + nt * 512 + c0;
                        *(uint4*)(dst)      = u[0];
                        *(uint4*)(dst + 8)  = u[1];
                        *(uint4*)(dst + 16) = v[0];
                        *(uint4*)(dst + 24) = v[1];
                    } else {
                        float* dst = outp + (size_t)grow * NN + nt * 512 + c0;
#pragma unroll
                        for (int q = 0; q < 8; q++) {
                            float4 v4 = make_float4(__uint_as_float(r[4 * q + 0]), __uint_as_float(r[4 * q + 1]),
                                                    __uint_as_float(r[4 * q + 2]), __uint_as_float(r[4 * q + 3]));
                            *(float4*)(dst + 4 * q) = v4;
                        }
                    }
                }
            }
            asm volatile("bar.sync 1, 128;" ::: "memory");
            if (tid == 0) MBARRIER_ARRIVE_LEADER(mb_free);
        }
    }

    __syncthreads();
    if (wid == 4) TCGEN05_DEALLOC_CG2(tmem, 512);
    CLUSTER_SYNC();
#endif // HAS_TCGEN05
}

// ================= HMMA fallback (compiles everywhere) ========================
__device__ __forceinline__ void ldsm4(uint32_t& r0, uint32_t& r1, uint32_t& r2, uint32_t& r3, uint32_t a) {
    asm volatile("ldmatrix.sync.aligned.m8n8.x4.shared.b16 {%0,%1,%2,%3}, [%4];\n"
                 : "=r"(r0), "=r"(r1), "=r"(r2), "=r"(r3) : "r"(a));
}
__device__ __forceinline__ void mma16816(float* c, uint32_t a0, uint32_t a1, uint32_t a2, uint32_t a3,
                                         uint32_t b0, uint32_t b1) {
    asm volatile(
        "mma.sync.aligned.m16n8k16.row.col.f32.f16.f16.f32 "
        "{%0,%1,%2,%3}, {%4,%5,%6,%7}, {%8,%9}, {%0,%1,%2,%3};\n"
        : "+f"(c[0]), "+f"(c[1]), "+f"(c[2]), "+f"(c[3])
        : "r"(a0), "r"(a1), "r"(a2), "r"(a3), "r"(b0), "r"(b1));
}

template <int MM, int NN, int KK, int WHICH>
__global__ void __launch_bounds__(256, 2) gemm_hmma(float* __restrict__ outp) {
    const __half* __restrict__ A = (WHICH == 1) ? g_A  : g_Z;
    const __half* __restrict__ B = (WHICH == 1) ? g_Wf : g_Wi;

    constexpr int FBM = 128, FBN = 128, FBK = 32;
    constexpr int LDT = FBK + 8;
    __shared__ __align__(16) __half As[2][FBM * LDT];
    __shared__ __align__(16) __half Bs[2][FBN * LDT];

    const int tid = threadIdx.x, lane = tid & 31, wid = tid >> 5;
    const int wm = wid & 3, wn = wid >> 2;
    const int bm = blockIdx.y * FBM, bn = blockIdx.x * FBN;

    float acc[2][8][4];
#pragma unroll
    for (int i = 0; i < 2; i++)
#pragma unroll
        for (int j = 0; j < 8; j++)
#pragma unroll
            for (int q = 0; q < 4; q++) acc[i][j][q] = 0.f;

    const int trow = tid >> 2, tcol = (tid & 3) << 3;
    auto load_tile = [&](int kt, int buf) {
        const int k0 = kt * FBK;
        const __half* ag = A + (size_t)(bm + trow) * KK + k0 + tcol;
        cp16(smem_u32(&As[buf][trow * LDT + tcol]), ag);
        cp16(smem_u32(&As[buf][(trow + 64) * LDT + tcol]), ag + (size_t)64 * KK);
        const __half* bg = B + (size_t)(bn + trow) * KK + k0 + tcol;
        cp16(smem_u32(&Bs[buf][trow * LDT + tcol]), bg);
        cp16(smem_u32(&Bs[buf][(trow + 64) * LDT + tcol]), bg + (size_t)64 * KK);
        cp_commit();
    };

    load_tile(0, 0);
    constexpr int KT = KK / FBK;
    for (int kt = 0; kt < KT; kt++) {
        const int buf = kt & 1;
        if (kt + 1 < KT) { load_tile(kt + 1, buf ^ 1); cp_wait<1>(); }
        else            { cp_wait<0>(); }
        __syncthreads();
#pragma unroll
        for (int ks = 0; ks < 2; ks++) {
            uint32_t a[2][4], b[4][4];
#pragma unroll
            for (int mt = 0; mt < 2; mt++) {
                int r = wm * 32 + mt * 16 + (lane & 15);
                int c = ks * 16 + ((lane >> 4) << 3);
                ldsm4(a[mt][0], a[mt][1], a[mt][2], a[mt][3], smem_u32(&As[buf][r * LDT + c]));
            }
#pragma unroll
            for (int nt = 0; nt < 4; nt++) {
                int r = wn * 64 + nt * 16 + (lane & 15);
                int c = ks * 16 + ((lane >> 4) << 3);
                ldsm4(b[nt][0], b[nt][1], b[nt][2], b[nt][3], smem_u32(&Bs[buf][r * LDT + c]));
            }
#pragma unroll
            for (int mt = 0; mt < 2; mt++)
#pragma unroll
                for (int nt = 0; nt < 8; nt++)
                    mma16816(acc[mt][nt], a[mt][0], a[mt][1], a[mt][2], a[mt][3],
                             b[nt >> 1][nt & 1], b[nt >> 1][(nt & 1) + 2]);
        }
        __syncthreads();
    }
#pragma unroll
    for (int mt = 0; mt < 2; mt++)
#pragma unroll
        for (int nt = 0; nt < 8; nt++) {
            int row = bm + wm * 32 + mt * 16 + (lane >> 2);
            int col = bn + wn * 64 + nt * 8 + ((lane & 3) << 1);
            if (WHICH == 1) {
                g_X[(size_t)row * NN + col]           = __float2half_rn(acc[mt][nt][0]);
                g_X[(size_t)row * NN + col + 1]       = __float2half_rn(acc[mt][nt][1]);
                g_X[(size_t)(row + 8) * NN + col]     = __float2half_rn(acc[mt][nt][2]);
                g_X[(size_t)(row + 8) * NN + col + 1] = __float2half_rn(acc[mt][nt][3]);
            } else {
                outp[(size_t)row * NN + col]           = acc[mt][nt][0];
                outp[(size_t)row * NN + col + 1]       = acc[mt][nt][1];
                outp[(size_t)(row + 8) * NN + col]     = acc[mt][nt][2];
                outp[(size_t)(row + 8) * NN + col + 1] = acc[mt][nt][3];
            }
        }
}

// ---------------- host: tensor-map encoding via dlopen ------------------------
typedef CUresult (*EncodeFn)(CUtensorMap*, CUtensorMapDataType, cuuint32_t, void*,
                             const cuuint64_t*, const cuuint64_t*, const cuuint32_t*,
                             const cuuint32_t*, CUtensorMapInterleave, CUtensorMapSwizzle,
                             CUtensorMapL2promotion, CUtensorMapFloatOOBfill);
static EncodeFn get_encoder() {
    static EncodeFn fn = nullptr;
    static bool tried = false;
    if (!tried) {
        tried = true;
        void* h = dlopen("libcuda.so.1", RTLD_LAZY | RTLD_GLOBAL);
        if (!h) h = dlopen("libcuda.so", RTLD_LAZY | RTLD_GLOBAL);
        if (h) fn = (EncodeFn)dlsym(h, "cuTensorMapEncodeTiled");
    }
    return fn;
}
static bool encode_tm(CUtensorMap* tm, void* base, uint64_t rows, uint64_t cols) {
    EncodeFn fn = get_encoder();
    if (!fn || !base) return false;
    cuuint64_t dims[3]    = {cols, rows, 1};
    cuuint64_t strides[2] = {cols * 2, cols * rows * 2};
    cuuint32_t box[3]     = {64, 128, 1};
    cuuint32_t es[3]      = {1, 1, 1};
    return fn(tm, CU_TENSOR_MAP_DATA_TYPE_FLOAT16, 3, base, dims, strides, box, es,
              CU_TENSOR_MAP_INTERLEAVE_NONE, CU_TENSOR_MAP_SWIZZLE_128B,
              CU_TENSOR_MAP_L2_PROMOTION_L2_128B,
              CU_TENSOR_MAP_FLOAT_OOB_FILL_NONE) == CUDA_SUCCESS;
}

// ---------------- launch -------------------------------------------------------
extern "C" void kernel_launch(void* const* d_in, const int* in_sizes, int n_in,
                              void* d_out, int out_size) {
    const float* x = (const float*)d_in[0];
    const float* k = (const float*)d_in[1];
    float* out = (float*)d_out;

    cudaFuncAttributes fa{};
    bool use_tc = (cudaFuncGetAttributes(&fa, (const void*)gemm_tma4<K1, 1>) == cudaSuccess)
                  && (fa.numRegs >= 40);

    static CUtensorMap tmA1, tmB1, tmA2, tmB2;
    static int tm_state = 0;
    if (use_tc && tm_state == 0) {
        void *pA = nullptr, *pWf = nullptr, *pWi = nullptr, *pZ = nullptr;
        cudaGetSymbolAddress(&pA,  g_A);
        cudaGetSymbolAddress(&pWf, g_Wf);
        cudaGetSymbolAddress(&pWi, g_Wi);
        cudaGetSymbolAddress(&pZ,  g_Z);
        bool ok = encode_tm(&tmA1, pA,  M1, K1)
               && encode_tm(&tmB1, pWf, N1, K1)
               && encode_tm(&tmA2, pZ,  M2, K2)
               && encode_tm(&tmB2, pWi, N2, K2);
        tm_state = ok ? 1 : -1;
    }
    if (tm_state != 1) use_tc = false;

    pre_convert_fillwf<<<CV_BLOCKS + (N1 * K1 / 8) / 256, 256>>>(
        (const float4*)x, (const float4*)k);

    if (use_tc) {
        cudaFuncSetAttribute((const void*)gemm_tma4<K1, 1>,
                             cudaFuncAttributeMaxDynamicSharedMemorySize, SMEM_DYN);
        cudaFuncSetAttribute((const void*)gemm_tma4<K2, 2>,
                             cudaFuncAttributeMaxDynamicSharedMemorySize, SMEM_DYN);
        gemm_tma4<K1, 1><<<dim3(4 * NCL4, 1), 256, SMEM_DYN>>>(nullptr, tmA1, tmB1);
        mid_pointwise_fillwi<<<PW_BLOCKS + (N2 * K2 / 8) / 256, 256>>>();
        gemm_tma4<K2, 2><<<dim3(4 * NCL4, 1), 256, SMEM_DYN>>>(out, tmA2, tmB2);
    } else {
        gemm_hmma<M1, N1, K1, 1><<<dim3(N1 / 128, M1 / 128), 256>>>(nullptr);
        mid_pointwise_fillwi<<<PW_BLOCKS + (N2 * K2 / 8) / 256, 256>>>();
        gemm_hmma<M2, N2, K2, 2><<<dim3(N2 / 128, M2 / 128), 256>>>(out);
    }
}